// round 6
// baseline (speedup 1.0000x reference)
#include <cuda_runtime.h>
#include <cuda_bf16.h>
#include <cstdint>

// Problem constants
#define T_STEPS 500
#define B_SZ    128
#define K_SZ    256
#define F_SZ    512
#define C_SZ    10
#define MROWS   (T_STEPS * B_SZ)   // 64000
#define NEURONS (B_SZ * F_SZ)      // 65536

// GEMM tiling: CTA 128(M) x 128(N), 16 warps of 32x32, K chunk 64, 3 bf16 terms.
#define TM 128
#define TN 128
#define KC 64
#define NCHUNK (K_SZ / KC)   // 4
#define GT 512               // GEMM threads (16 warps)

// Padded smem rows: 64 data bf16 + 8 pad = 72 bf16 = 144 B (conflict-free ldmatrix)
#define PITCHB     144
#define TILEBYTES  (128 * PITCHB)      // 18432 per (array, stage)
#define STAGEBYTES (4 * TILEBYTES)     // Ahi, Alo, Bhi, Blo
#define SMEM_TOTAL (2 * STAGEBYTES)    // double buffered = 147456 B

// Scratch
__device__ float g_proj[MROWS * F_SZ];            // 131 MB
__device__ float g_counts[NEURONS];
__device__ __nv_bfloat16 g_xhi[MROWS * K_SZ];     // 32.8 MB
__device__ __nv_bfloat16 g_xlo[MROWS * K_SZ];
__device__ __nv_bfloat16 g_whi[F_SZ * K_SZ];
__device__ __nv_bfloat16 g_wlo[F_SZ * K_SZ];

// ---------------- helpers ----------------
__device__ __forceinline__ uint32_t smem_u32(const void* p) {
    uint32_t a;
    asm("{ .reg .u64 t; cvta.to.shared.u64 t, %1; cvt.u32.u64 %0, t; }" : "=r"(a) : "l"(p));
    return a;
}
__device__ __forceinline__ void cp_async16(uint32_t dst, const void* src) {
    asm volatile("cp.async.cg.shared.global [%0], [%1], 16;" :: "r"(dst), "l"(src) : "memory");
}
#define CP_COMMIT() asm volatile("cp.async.commit_group;" ::: "memory")

__device__ __forceinline__ void ldmx4(uint32_t* r, uint32_t addr) {
    asm volatile("ldmatrix.sync.aligned.m8n8.x4.shared.b16 {%0,%1,%2,%3}, [%4];"
                 : "=r"(r[0]), "=r"(r[1]), "=r"(r[2]), "=r"(r[3]) : "r"(addr));
}
__device__ __forceinline__ void mma_bf16(float* c, const uint32_t* a, const uint32_t* b) {
    asm volatile(
        "mma.sync.aligned.m16n8k16.row.col.f32.bf16.bf16.f32 "
        "{%0,%1,%2,%3}, {%4,%5,%6,%7}, {%8,%9}, {%0,%1,%2,%3};"
        : "+f"(c[0]), "+f"(c[1]), "+f"(c[2]), "+f"(c[3])
        : "r"(a[0]), "r"(a[1]), "r"(a[2]), "r"(a[3]), "r"(b[0]), "r"(b[1]));
}

// ---------------- Pass 0: fp32 -> bf16 hi/lo split (x and W in one launch) ----------------
__global__ void convert_split_kernel(const float4* __restrict__ xsrc, int nx4,
                                     const float4* __restrict__ wsrc, int nw4,
                                     uint2* __restrict__ xhi, uint2* __restrict__ xlo,
                                     uint2* __restrict__ whi, uint2* __restrict__ wlo)
{
    int i = blockIdx.x * blockDim.x + threadIdx.x;
    const float4* src; uint2* hi; uint2* lo; int idx;
    if (i < nx4)            { src = xsrc; hi = xhi; lo = xlo; idx = i; }
    else if (i < nx4 + nw4) { src = wsrc; hi = whi; lo = wlo; idx = i - nx4; }
    else return;
    float4 v = src[idx];
    __nv_bfloat16 h0 = __float2bfloat16(v.x), h1 = __float2bfloat16(v.y);
    __nv_bfloat16 h2 = __float2bfloat16(v.z), h3 = __float2bfloat16(v.w);
    __nv_bfloat16 l0 = __float2bfloat16(v.x - __bfloat162float(h0));
    __nv_bfloat16 l1 = __float2bfloat16(v.y - __bfloat162float(h1));
    __nv_bfloat16 l2 = __float2bfloat16(v.z - __bfloat162float(h2));
    __nv_bfloat16 l3 = __float2bfloat16(v.w - __bfloat162float(h3));
    uint2 ph, pl;
    ph.x = (uint32_t)*(uint16_t*)&h0 | ((uint32_t)*(uint16_t*)&h1 << 16);
    ph.y = (uint32_t)*(uint16_t*)&h2 | ((uint32_t)*(uint16_t*)&h3 << 16);
    pl.x = (uint32_t)*(uint16_t*)&l0 | ((uint32_t)*(uint16_t*)&l1 << 16);
    pl.y = (uint32_t)*(uint16_t*)&l2 | ((uint32_t)*(uint16_t*)&l3 << 16);
    hi[idx] = ph;
    lo[idx] = pl;
}

// ---------------- Pass 1: GEMM proj = x @ W^T via mma.sync bf16 ----------------
__device__ __forceinline__ void stage_chunk(uint32_t sb, int s, int c,
                                            int mtile, int ntile, int tid)
{
    // 512 threads: r = tid>>3 (0..63), u = tid&7. Two 64-row passes per array.
    const int r = tid >> 3;
    const int u = tid & 7;
    #pragma unroll
    for (int pass = 0; pass < 2; ++pass) {
        const int row = pass * 64 + r;
        const uint32_t d = sb + s * STAGEBYTES + row * PITCHB + u * 16;
        const size_t aoff = (size_t)(mtile * TM + row) * K_SZ + c * KC + u * 8;
        const size_t boff = (size_t)(ntile * TN + row) * K_SZ + c * KC + u * 8;
        cp_async16(d,                 g_xhi + aoff);
        cp_async16(d + TILEBYTES,     g_xlo + aoff);
        cp_async16(d + 2 * TILEBYTES, g_whi + boff);
        cp_async16(d + 3 * TILEBYTES, g_wlo + boff);
    }
}

__global__ __launch_bounds__(GT, 1)
void snn_gemm_kernel()
{
    extern __shared__ char smem[];
    const uint32_t sb = smem_u32(smem);
    const int tid  = threadIdx.x;
    const int lane = tid & 31;
    const int wid  = tid >> 5;      // 0..15
    const int wm   = wid >> 2;      // 0..3 -> 32-row block
    const int wn   = wid & 3;       // 0..3 -> 32-col block
    const int mtile = blockIdx.x;   // 0..499
    const int ntile = blockIdx.y;   // 0..3

    const uint32_t laneoff = (uint32_t)((lane & 15) * PITCHB + (lane >> 4) * 16);

    float acc[2][4][4];
    #pragma unroll
    for (int mi = 0; mi < 2; ++mi)
        #pragma unroll
        for (int ni = 0; ni < 4; ++ni)
            #pragma unroll
            for (int q = 0; q < 4; ++q) acc[mi][ni][q] = 0.f;

    stage_chunk(sb, 0, 0, mtile, ntile, tid);
    CP_COMMIT();

    for (int c = 0; c < NCHUNK; ++c) {
        const int s = c & 1;
        if (c + 1 < NCHUNK) {
            stage_chunk(sb, s ^ 1, c + 1, mtile, ntile, tid);
            CP_COMMIT();
            asm volatile("cp.async.wait_group 1;" ::: "memory");
        } else {
            asm volatile("cp.async.wait_group 0;" ::: "memory");
        }
        __syncthreads();

        const uint32_t Ahi_b = sb + s * STAGEBYTES;
        const uint32_t Bhi_b = Ahi_b + 2 * TILEBYTES;

        #pragma unroll
        for (int kk = 0; kk < 4; ++kk) {
            uint32_t ah[2][4], al[2][4];
            #pragma unroll
            for (int mi = 0; mi < 2; ++mi) {
                uint32_t addr = Ahi_b + (uint32_t)((wm * 32 + mi * 16) * PITCHB + kk * 32) + laneoff;
                ldmx4(ah[mi], addr);
                ldmx4(al[mi], addr + TILEBYTES);
            }
            uint32_t bh[4][2], bl[4][2];
            #pragma unroll
            for (int p = 0; p < 2; ++p) {
                uint32_t addr = Bhi_b + (uint32_t)((wn * 32 + p * 16) * PITCHB + kk * 32) + laneoff;
                uint32_t r[4];
                ldmx4(r, addr);
                bh[2*p][0] = r[0]; bh[2*p][1] = r[2];
                bh[2*p+1][0] = r[1]; bh[2*p+1][1] = r[3];
                ldmx4(r, addr + TILEBYTES);
                bl[2*p][0] = r[0]; bl[2*p][1] = r[2];
                bl[2*p+1][0] = r[1]; bl[2*p+1][1] = r[3];
            }
            #pragma unroll
            for (int mi = 0; mi < 2; ++mi)
                #pragma unroll
                for (int ni = 0; ni < 4; ++ni) {
                    mma_bf16(acc[mi][ni], ah[mi], bh[ni]);   // xh * wh
                    mma_bf16(acc[mi][ni], ah[mi], bl[ni]);   // xh * wl
                    mma_bf16(acc[mi][ni], al[mi], bh[ni]);   // xl * wh
                }
        }
        __syncthreads();
    }

    // Epilogue: fragment -> gmem (float2 stores)
    const int g  = lane >> 2;
    const int tg = lane & 3;
    #pragma unroll
    for (int mi = 0; mi < 2; ++mi) {
        const int m0 = mtile * TM + wm * 32 + mi * 16 + g;
        #pragma unroll
        for (int ni = 0; ni < 4; ++ni) {
            const int nc = ntile * TN + wn * 32 + ni * 8 + tg * 2;
            float2 v0 = make_float2(acc[mi][ni][0], acc[mi][ni][1]);
            float2 v1 = make_float2(acc[mi][ni][2], acc[mi][ni][3]);
            *reinterpret_cast<float2*>(&g_proj[(size_t)m0 * F_SZ + nc])       = v0;
            *reinterpret_cast<float2*>(&g_proj[(size_t)(m0 + 8) * F_SZ + nc]) = v1;
        }
    }
}

// ---------------- Pass 2: LIF scan (2 neurons/thread, deep MLP) ----------------
#define SCAN_UNROLL 16
__global__ __launch_bounds__(512, 2)
void snn_scan_kernel()
{
    const int i = blockIdx.x * 512 + threadIdx.x;      // 0..32767
    const float2* p = reinterpret_cast<const float2*>(g_proj) + i;
    float u0 = 0.f, tr0 = 0.f, c0 = 0.f;
    float u1 = 0.f, tr1 = 0.f, c1 = 0.f;
    #pragma unroll 1
    for (int t = 0; t < T_STEPS; t += SCAN_UNROLL) {
        float2 v[SCAN_UNROLL];
        // 500 % 16 = 4: guard the tail reads but keep the batch in flight.
        #pragma unroll
        for (int j = 0; j < SCAN_UNROLL; ++j)
            v[j] = (t + j < T_STEPS) ? p[(size_t)(t + j) * (NEURONS / 2)]
                                     : make_float2(0.f, 0.f);
        #pragma unroll
        for (int j = 0; j < SCAN_UNROLL; ++j) {
            if (t + j < T_STEPS) {
                tr0 = 0.95f * tr0 + v[j].x;
                u0  = 0.90f * u0 + tr0;
                if (u0 > 1.0f) { c0 += 1.0f; u0 = 0.0f; }
                tr1 = 0.95f * tr1 + v[j].y;
                u1  = 0.90f * u1 + tr1;
                if (u1 > 1.0f) { c1 += 1.0f; u1 = 0.0f; }
            }
        }
    }
    g_counts[2 * i]     = c0;
    g_counts[2 * i + 1] = c1;
}

// ---------------- Pass 3: decoder ----------------
__global__ __launch_bounds__(320, 1)
void snn_decode_kernel(const float* __restrict__ dec_w,
                       const float* __restrict__ dec_b,
                       float* __restrict__ out)
{
    const int b = blockIdx.x;
    const int c = threadIdx.x >> 5;
    const int l = threadIdx.x & 31;
    const float* cnt = g_counts + (size_t)b * F_SZ;
    const float* dwr = dec_w + (size_t)c * F_SZ;
    float s = 0.f;
    #pragma unroll
    for (int fi = l; fi < F_SZ; fi += 32)
        s += cnt[fi] * dwr[fi];
    #pragma unroll
    for (int o = 16; o > 0; o >>= 1)
        s += __shfl_down_sync(0xffffffffu, s, o);
    if (l == 0)
        out[b * C_SZ + c] = s + dec_b[c];
}

extern "C" void kernel_launch(void* const* d_in, const int* in_sizes, int n_in,
                              void* d_out, int out_size)
{
    const float* x     = (const float*)d_in[0];
    const float* wts   = (const float*)d_in[1];
    const float* dec_w = (const float*)d_in[2];
    const float* dec_b = (const float*)d_in[3];
    float* out = (float*)d_out;

    static uint2* p_xhi = nullptr; static uint2* p_xlo = nullptr;
    static uint2* p_whi = nullptr; static uint2* p_wlo = nullptr;
    if (!p_xhi) {
        cudaGetSymbolAddress((void**)&p_xhi, g_xhi);
        cudaGetSymbolAddress((void**)&p_xlo, g_xlo);
        cudaGetSymbolAddress((void**)&p_whi, g_whi);
        cudaGetSymbolAddress((void**)&p_wlo, g_wlo);
        cudaFuncSetAttribute(snn_gemm_kernel,
                             cudaFuncAttributeMaxDynamicSharedMemorySize, SMEM_TOTAL);
    }

    const int nx4 = MROWS * K_SZ / 4;   // 4,096,000
    const int nw4 = F_SZ * K_SZ / 4;    // 32,768
    convert_split_kernel<<<(nx4 + nw4 + 255) / 256, 256>>>(
        (const float4*)x, nx4, (const float4*)wts, nw4, p_xhi, p_xlo, p_whi, p_wlo);

    dim3 grid(MROWS / TM, F_SZ / TN);   // (500, 4)
    snn_gemm_kernel<<<grid, GT, SMEM_TOTAL>>>();
    snn_scan_kernel<<<NEURONS / 2 / 512, 512>>>();
    snn_decode_kernel<<<B_SZ, 320>>>(dec_w, dec_b, out);
}